// round 16
// baseline (speedup 1.0000x reference)
#include <cuda_runtime.h>
#include <cuda_bf16.h>
#include <cstdint>

#define Tn   197
#define Bn   64
#define Fn   768
#define Gn   192
#define Nn   8
#define CAPn 49
#define Hn   3072
#define Pn   (Tn*Bn)
#define MRV  (Bn*CAPn)
#define MR   3200

__device__ __nv_bfloat16 g_xb [Pn*Fn];     // x hi (bf16)
__device__ __nv_bfloat16 g_xl [Pn*Fn];     // x lo residual (bf16)
__device__ __nv_bfloat16 g_wg1h[Fn*Gn];    // Wg1 hi
__device__ __nv_bfloat16 g_wg1l[Fn*Gn];    // Wg1 lo
__device__ __nv_bfloat16 g_W1b[Nn*Fn*Hn];
__device__ __nv_bfloat16 g_W2b[Nn*Hn*Fn];
__device__ float         g_gate[Pn*Gn];
__device__ float         g_cw  [Pn*Nn];
__device__ int           g_tok [Nn*MR];
__device__ float         g_wgt [Nn*MR];
__device__ __nv_bfloat16 g_H   [(size_t)Nn*MR*Hn];

// fp32 -> bf16, 8 elems/thread (2 independent float4 loads -> MLP 2)
__global__ void cvt_kernel(const float* __restrict__ s, __nv_bfloat16* __restrict__ d, int n)
{
    int i = (blockIdx.x * 256 + threadIdx.x) * 8;
    if (i < n) {
        float4 v0 = *(const float4*)(s + i);
        float4 v1 = *(const float4*)(s + i + 4);
        *(__nv_bfloat162*)(d + i)     = __floats2bfloat162_rn(v0.x, v0.y);
        *(__nv_bfloat162*)(d + i + 2) = __floats2bfloat162_rn(v0.z, v0.w);
        *(__nv_bfloat162*)(d + i + 4) = __floats2bfloat162_rn(v1.x, v1.y);
        *(__nv_bfloat162*)(d + i + 6) = __floats2bfloat162_rn(v1.z, v1.w);
    }
}

// fp32 -> (hi bf16, lo bf16 residual), 8 elems/thread (MLP 2)
__global__ void cvt_split_kernel(const float* __restrict__ s,
                                 __nv_bfloat16* __restrict__ hi,
                                 __nv_bfloat16* __restrict__ lo, int n)
{
    int i = (blockIdx.x * 256 + threadIdx.x) * 8;
    if (i < n) {
        float4 v0 = *(const float4*)(s + i);
        float4 v1 = *(const float4*)(s + i + 4);
        float f[8] = {v0.x, v0.y, v0.z, v0.w, v1.x, v1.y, v1.z, v1.w};
        __nv_bfloat16 h[8], l[8];
#pragma unroll
        for (int j = 0; j < 8; j++) {
            h[j] = __float2bfloat16(f[j]);
            l[j] = __float2bfloat16(f[j] - __bfloat162float(h[j]));
        }
#pragma unroll
        for (int j = 0; j < 8; j += 2) {
            *(__nv_bfloat162*)(hi + i + j) = *(__nv_bfloat162*)&h[j];
            *(__nv_bfloat162*)(lo + i + j) = *(__nv_bfloat162*)&l[j];
        }
    }
}

// -------- mma.sync helpers --------
__device__ __forceinline__ void ldsm4(uint32_t r[4], uint32_t addr)
{
    asm volatile("ldmatrix.sync.aligned.m8n8.x4.shared.b16 {%0,%1,%2,%3}, [%4];"
                 : "=r"(r[0]), "=r"(r[1]), "=r"(r[2]), "=r"(r[3]) : "r"(addr));
}
__device__ __forceinline__ void ldsm4t(uint32_t r[4], uint32_t addr)
{
    asm volatile("ldmatrix.sync.aligned.m8n8.x4.trans.shared.b16 {%0,%1,%2,%3}, [%4];"
                 : "=r"(r[0]), "=r"(r[1]), "=r"(r[2]), "=r"(r[3]) : "r"(addr));
}
__device__ __forceinline__ void mma16816(float c[4], const uint32_t a[4], uint32_t b0, uint32_t b1)
{
    asm volatile("mma.sync.aligned.m16n8k16.row.col.f32.bf16.bf16.f32 "
                 "{%0,%1,%2,%3},{%4,%5,%6,%7},{%8,%9},{%0,%1,%2,%3};"
                 : "+f"(c[0]), "+f"(c[1]), "+f"(c[2]), "+f"(c[3])
                 : "r"(a[0]), "r"(a[1]), "r"(a[2]), "r"(a[3]), "r"(b0), "r"(b1));
}
__device__ __forceinline__ void cpasync16(uint32_t saddr, const void* g, int sz)
{
    asm volatile("cp.async.cg.shared.global [%0], [%1], 16, %2;" :: "r"(saddr), "l"(g), "r"(sz));
}

// gate layer 1 via split-bf16 tensor cores
__global__ void __launch_bounds__(256) gate1_tc_kernel(const float* __restrict__ bg1)
{
    __shared__ __align__(16) __nv_bfloat16 sAh[2][128 * 24];
    __shared__ __align__(16) __nv_bfloat16 sAl[2][128 * 24];
    __shared__ __align__(16) __nv_bfloat16 sBh[2][16 * 72];
    __shared__ __align__(16) __nv_bfloat16 sBl[2][16 * 72];

    const int m0 = blockIdx.x * 128;
    const int n0 = blockIdx.y * 64;
    const int tid = threadIdx.x;
    const int lane = tid & 31;
    const int warp = tid >> 5;
    const int wm = warp >> 1, wn = warp & 1;

    int rowA = tid >> 1, cA = (tid & 1) * 8;
    int szA = (m0 + rowA < Pn) ? 16 : 0;
    int rA = (m0 + rowA < Pn) ? (m0 + rowA) : 0;
    const __nv_bfloat16* aph = g_xb + (size_t)rA * Fn + cA;
    const __nv_bfloat16* apl = g_xl + (size_t)rA * Fn + cA;
    int tb = tid & 127;
    int rowB = tb >> 3, cB = (tb & 7) * 8;
    const __nv_bfloat16* bp = (tid < 128 ? g_wg1h : g_wg1l) + (size_t)rowB * Gn + n0 + cB;

    uint32_t sAhB = (uint32_t)__cvta_generic_to_shared(&sAh[0][0]);
    uint32_t sAlB = (uint32_t)__cvta_generic_to_shared(&sAl[0][0]);
    uint32_t sBhB = (uint32_t)__cvta_generic_to_shared(&sBh[0][0]);
    uint32_t sBlB = (uint32_t)__cvta_generic_to_shared(&sBl[0][0]);
    const uint32_t stA = 128 * 24 * 2, stB = 16 * 72 * 2;
    uint32_t dAh = sAhB + (rowA * 24 + cA) * 2;
    uint32_t dAl = sAlB + (rowA * 24 + cA) * 2;
    uint32_t dB  = (tid < 128 ? sBhB : sBlB) + (rowB * 72 + cB) * 2;

    float acc[2][4][4] = {};
    constexpr int NK = Fn / 16;

    auto load_stage = [&](int buf, int kt) {
        int ko = kt * 16;
        cpasync16(dAh + buf * stA, aph + ko, szA);
        cpasync16(dAl + buf * stA, apl + ko, szA);
        cpasync16(dB  + buf * stB, bp + (size_t)ko * Gn, 16);
    };

    load_stage(0, 0);
    asm volatile("cp.async.commit_group;");

    uint32_t aoff = ((wm * 32 + (lane & 15)) * 24 + (lane >> 4) * 8) * 2;
    uint32_t boff = (((lane & 7) + ((lane >> 3) & 1) * 8) * 72 + wn * 32 + (lane >> 4) * 8) * 2;

    for (int kt = 0; kt < NK; ++kt) {
        if (kt + 1 < NK) load_stage((kt + 1) & 1, kt + 1);
        asm volatile("cp.async.commit_group;");
        asm volatile("cp.async.wait_group 1;");
        __syncthreads();

        int buf = kt & 1;
        uint32_t ah[2][4], al[2][4], bh[2][4], bl[2][4];
#pragma unroll
        for (int mi = 0; mi < 2; mi++) {
            ldsm4(ah[mi], sAhB + buf * stA + aoff + mi * 16 * 24 * 2);
            ldsm4(al[mi], sAlB + buf * stA + aoff + mi * 16 * 24 * 2);
        }
#pragma unroll
        for (int nj = 0; nj < 2; nj++) {
            ldsm4t(bh[nj], sBhB + buf * stB + boff + nj * 16 * 2);
            ldsm4t(bl[nj], sBlB + buf * stB + boff + nj * 16 * 2);
        }
#pragma unroll
        for (int mi = 0; mi < 2; mi++)
#pragma unroll
            for (int ni = 0; ni < 4; ni++) {
                int sl = ni >> 1, pp = (ni & 1) * 2;
                mma16816(acc[mi][ni], ah[mi], bh[sl][pp], bh[sl][pp + 1]);
                mma16816(acc[mi][ni], ah[mi], bl[sl][pp], bl[sl][pp + 1]);
                mma16816(acc[mi][ni], al[mi], bh[sl][pp], bh[sl][pp + 1]);
            }
        __syncthreads();
    }

    int gq = lane >> 2, t2 = lane & 3;
#pragma unroll
    for (int mi = 0; mi < 2; mi++) {
        int mlo = m0 + wm * 32 + mi * 16 + gq;
#pragma unroll
        for (int ni = 0; ni < 4; ni++) {
            int col = n0 + wn * 32 + ni * 8 + t2 * 2;
            float b0 = bg1[col], b1 = bg1[col + 1];
            if (mlo < Pn) {
                g_gate[(size_t)mlo * Gn + col]     = fmaxf(acc[mi][ni][0] + b0, 0.f);
                g_gate[(size_t)mlo * Gn + col + 1] = fmaxf(acc[mi][ni][1] + b1, 0.f);
            }
            if (mlo + 8 < Pn) {
                g_gate[(size_t)(mlo + 8) * Gn + col]     = fmaxf(acc[mi][ni][2] + b0, 0.f);
                g_gate[(size_t)(mlo + 8) * Gn + col + 1] = fmaxf(acc[mi][ni][3] + b1, 0.f);
            }
        }
    }
}

// gate layer 2 + softmax + top-2 (warp per token)
__global__ void gate2_kernel(const float* __restrict__ Wg2, const float* __restrict__ bg2)
{
    int tokw = blockIdx.x * 8 + (threadIdx.x >> 5);
    if (tokw >= Pn) return;
    int lane = threadIdx.x & 31;
    const float* g = g_gate + (size_t)tokw * Gn;

    float s[8] = {};
    for (int j = lane; j < Gn; j += 32) {
        float gv = g[j];
        float4 w0 = *(const float4*)(Wg2 + j * 8);
        float4 w1 = *(const float4*)(Wg2 + j * 8 + 4);
        s[0] += gv * w0.x; s[1] += gv * w0.y; s[2] += gv * w0.z; s[3] += gv * w0.w;
        s[4] += gv * w1.x; s[5] += gv * w1.y; s[6] += gv * w1.z; s[7] += gv * w1.w;
    }
#pragma unroll
    for (int e = 0; e < 8; e++)
#pragma unroll
        for (int o = 16; o; o >>= 1) s[e] += __shfl_xor_sync(0xffffffffu, s[e], o);

    if (lane == 0) {
        float l[8], mx = -1e30f;
#pragma unroll
        for (int e = 0; e < 8; e++) { l[e] = s[e] + bg2[e]; mx = fmaxf(mx, l[e]); }
        float p[8], sum = 0.f;
#pragma unroll
        for (int e = 0; e < 8; e++) { p[e] = expf(l[e] - mx); sum += p[e]; }
        float inv = 1.f / sum, gwv[8];
#pragma unroll
        for (int e = 0; e < 8; e++) gwv[e] = p[e] * inv;
        int i1 = 0;
#pragma unroll
        for (int e = 1; e < 8; e++) if (gwv[e] > gwv[i1]) i1 = e;
        int i2 = (i1 == 0) ? 1 : 0;
#pragma unroll
        for (int e = 0; e < 8; e++) if (e != i1 && gwv[e] > gwv[i2]) i2 = e;
#pragma unroll
        for (int e = 0; e < 8; e++)
            g_cw[(size_t)tokw * 8 + e] = (e == i1 || e == i2) ? gwv[e] : 0.f;
    }
}

// capacity selection per (b,n): top-CAP by (value desc, index asc)
__global__ void cap_kernel()
{
    int b = blockIdx.x, n = blockIdx.y;
    __shared__ unsigned sb[Tn];
    __shared__ float    svv[Tn];
    __shared__ unsigned char sel[Tn];
    __shared__ int scnt;

    int t = threadIdx.x;
    if (t < Tn) {
        float v = g_cw[(size_t)(t * Bn + b) * Nn + n];
        svv[t] = v;
        sb[t] = __float_as_uint(v);
    }
    __syncthreads();

    bool is = false; float v = 0.f;
    if (t < Tn) {
        unsigned bt = sb[t];
        int rank = 0;
        for (int j = 0; j < Tn; j++) {
            unsigned bj = sb[j];
            rank += (bj > bt) || (bj == bt && j < t);
        }
        v = svv[t];
        is = (rank < CAPn) && (v > 0.f);
        sel[t] = is ? 1 : 0;
        g_cw[(size_t)(t * Bn + b) * Nn + n] = is ? v : 0.f;
    }
    __syncthreads();
    if (t == 0) {
        int c = 0;
        for (int j = 0; j < Tn; j++) c += sel[j];
        scnt = c;
    }
    __syncthreads();

    if (t < Tn && is) {
        int slot = 0;
        for (int j = 0; j < t; j++) slot += sel[j];
        g_tok[n * MR + b * CAPn + slot] = t * Bn + b;
        g_wgt[n * MR + b * CAPn + slot] = v;
    }
    if (t >= scnt && t < CAPn) {
        g_tok[n * MR + b * CAPn + t] = -1;
        g_wgt[n * MR + b * CAPn + t] = 0.f;
    }
    if (b == 0 && t < (MR - MRV)) {
        g_tok[n * MR + MRV + t] = -1;
        g_wgt[n * MR + MRV + t] = 0.f;
    }
}

// out = -x + fw @ b2
__global__ void init_out_kernel(const float* __restrict__ x, const float* __restrict__ b2,
                                float* __restrict__ out)
{
    int p = blockIdx.x;
    __shared__ float fw[8];
    if (threadIdx.x < 8) fw[threadIdx.x] = g_cw[(size_t)p * 8 + threadIdx.x];
    __syncthreads();
    for (int f = threadIdx.x; f < Fn; f += blockDim.x) {
        float s = -x[(size_t)p * Fn + f];
#pragma unroll
        for (int n = 0; n < 8; n++) s += fw[n] * b2[n * Fn + f];
        out[(size_t)p * Fn + f] = s;
    }
}

// 128x128x32 tile, 256 threads, 2x4 warps, 64x32 warp tile, 3-stage cp.async pipeline.
#define ASTG (128 * 40 * 2)
#define BSTG (32 * 136 * 2)
#define MOESMEM (3 * (ASTG + BSTG))
template<bool FIRST>
__global__ void __launch_bounds__(256, 2) moe_gemm_kernel(const float* __restrict__ bias,
                                                          float* __restrict__ out)
{
    constexpr int KTOT = FIRST ? Fn : Hn;
    constexpr int NBW  = FIRST ? Hn : Fn;
    constexpr int NK   = KTOT / 32;

    extern __shared__ __align__(16) char dynsmem[];
    uint32_t smb = (uint32_t)__cvta_generic_to_shared(dynsmem);

    const int nexp = blockIdx.z;
    const int m0 = blockIdx.x * 128;
    const int n0 = blockIdx.y * 128;
    const int tid = threadIdx.x;
    const int lane = tid & 31;
    const int warp = tid >> 5;
    const int wm = warp >> 2, wn = warp & 3;

    const __nv_bfloat16* Wn_ = (FIRST ? g_W1b : g_W2b) + (size_t)nexp * KTOT * NBW;

    int rowA0 = tid >> 2;
    int rowA1 = rowA0 + 64;
    int koA = (tid & 3) * 8;
    const __nv_bfloat16 *ap0, *ap1;
    int sz0 = 16, sz1 = 16;
    if (FIRST) {
        int t0 = g_tok[nexp * MR + m0 + rowA0];
        int t1 = g_tok[nexp * MR + m0 + rowA1];
        if (t0 < 0) { sz0 = 0; t0 = 0; }
        if (t1 < 0) { sz1 = 0; t1 = 0; }
        ap0 = g_xb + (size_t)t0 * Fn + koA;
        ap1 = g_xb + (size_t)t1 * Fn + koA;
    } else {
        ap0 = g_H + (size_t)(nexp * MR + m0 + rowA0) * Hn + koA;
        ap1 = g_H + (size_t)(nexp * MR + m0 + rowA1) * Hn + koA;
    }

    int krB = tid >> 4;
    int nqB = (tid & 15) * 8;
    const __nv_bfloat16* bp0 = Wn_ + (size_t)krB * NBW + n0 + nqB;
    const __nv_bfloat16* bp1 = Wn_ + (size_t)(krB + 16) * NBW + n0 + nqB;

    uint32_t dA0 = (rowA0 * 40 + koA) * 2;
    uint32_t dA1 = (rowA1 * 40 + koA) * 2;
    uint32_t dB0 = (krB * 136 + nqB) * 2;
    uint32_t dB1 = ((krB + 16) * 136 + nqB) * 2;

    auto sAst = [&](int s) { return smb + s * ASTG; };
    auto sBst = [&](int s) { return smb + 3 * ASTG + s * BSTG; };

    auto load_stage = [&](int s, int kt) {
        size_t ko = (size_t)kt * 32;
        cpasync16(sAst(s) + dA0, ap0 + ko, sz0);
        cpasync16(sAst(s) + dA1, ap1 + ko, sz1);
        cpasync16(sBst(s) + dB0, bp0 + ko * NBW, 16);
        cpasync16(sBst(s) + dB1, bp1 + ko * NBW, 16);
    };

    float acc[4][4][4] = {};

    load_stage(0, 0);
    asm volatile("cp.async.commit_group;");
    load_stage(1, 1);
    asm volatile("cp.async.commit_group;");

    uint32_t aoff = ((wm * 64 + (lane & 15)) * 40 + (lane >> 4) * 8) * 2;
    uint32_t boff = (((lane & 7) + ((lane >> 3) & 1) * 8) * 136 + wn * 32 + (lane >> 4) * 8) * 2;

    int st = 0, ld = 2;
    for (int kt = 0; kt < NK; ++kt) {
        asm volatile("cp.async.wait_group 1;");
        __syncthreads();
        if (ld < NK) {
            int ls = ld - 3 * (ld / 3);
            load_stage(ls, ld);
        }
        asm volatile("cp.async.commit_group;");
        ld++;

        uint32_t aAddr = sAst(st) + aoff;
        uint32_t bAddr = sBst(st) + boff;
#pragma unroll
        for (int ks = 0; ks < 2; ++ks) {
            uint32_t a[4][4];
#pragma unroll
            for (int mi = 0; mi < 4; mi++) ldsm4(a[mi], aAddr + (mi * 16 * 40 + ks * 16) * 2);
            uint32_t bfr[2][4];
#pragma unroll
            for (int nj = 0; nj < 2; nj++) ldsm4t(bfr[nj], bAddr + (ks * 16 * 136 + nj * 16) * 2);
#pragma unroll
            for (int mi = 0; mi < 4; mi++)
#pragma unroll
                for (int ni = 0; ni < 4; ni++)
                    mma16816(acc[mi][ni], a[mi],
                             bfr[ni >> 1][(ni & 1) * 2], bfr[ni >> 1][(ni & 1) * 2 + 1]);
        }
        st = (st == 2) ? 0 : st + 1;
    }

    int gq = lane >> 2, t2 = lane & 3;
    if (FIRST) {
#pragma unroll
        for (int mi = 0; mi < 4; mi++) {
            int mlo = m0 + wm * 64 + mi * 16 + gq;
#pragma unroll
            for (int ni = 0; ni < 4; ni++) {
                int col = n0 + wn * 32 + ni * 8 + t2 * 2;
                float bv0 = bias[nexp * Hn + col];
                float bv1 = bias[nexp * Hn + col + 1];
                *(__nv_bfloat162*)&g_H[(size_t)(nexp * MR + mlo) * Hn + col] =
                    __floats2bfloat162_rn(fmaxf(acc[mi][ni][0] + bv0, 0.f),
                                          fmaxf(acc[mi][ni][1] + bv1, 0.f));
                *(__nv_bfloat162*)&g_H[(size_t)(nexp * MR + mlo + 8) * Hn + col] =
                    __floats2bfloat162_rn(fmaxf(acc[mi][ni][2] + bv0, 0.f),
                                          fmaxf(acc[mi][ni][3] + bv1, 0.f));
            }
        }
    } else {
#pragma unroll
        for (int mi = 0; mi < 4; mi++) {
            int rlo = m0 + wm * 64 + mi * 16 + gq;
            int tokLo = g_tok[nexp * MR + rlo];
            int tokHi = g_tok[nexp * MR + rlo + 8];
            float wLo = g_wgt[nexp * MR + rlo];
            float wHi = g_wgt[nexp * MR + rlo + 8];
#pragma unroll
            for (int ni = 0; ni < 4; ni++) {
                int col = n0 + wn * 32 + ni * 8 + t2 * 2;
                if (tokLo >= 0) {
                    atomicAdd(out + (size_t)tokLo * Fn + col,     acc[mi][ni][0] * wLo);
                    atomicAdd(out + (size_t)tokLo * Fn + col + 1, acc[mi][ni][1] * wLo);
                }
                if (tokHi >= 0) {
                    atomicAdd(out + (size_t)tokHi * Fn + col,     acc[mi][ni][2] * wHi);
                    atomicAdd(out + (size_t)tokHi * Fn + col + 1, acc[mi][ni][3] * wHi);
                }
            }
        }
    }
}

extern "C" void kernel_launch(void* const* d_in, const int* in_sizes, int n_in,
                              void* d_out, int out_size)
{
    const float* x   = (const float*)d_in[0];
    const float* Wg1 = (const float*)d_in[1];
    const float* bg1 = (const float*)d_in[2];
    const float* Wg2 = (const float*)d_in[3];
    const float* bg2 = (const float*)d_in[4];
    const float* W1  = (const float*)d_in[5];
    const float* b1  = (const float*)d_in[6];
    const float* W2  = (const float*)d_in[7];
    const float* b2  = (const float*)d_in[8];
    float* out = (float*)d_out;

    void *xb_p, *xl_p, *wh_p, *wl_p, *w1b_p, *w2b_p;
    cudaGetSymbolAddress(&xb_p,  g_xb);
    cudaGetSymbolAddress(&xl_p,  g_xl);
    cudaGetSymbolAddress(&wh_p,  g_wg1h);
    cudaGetSymbolAddress(&wl_p,  g_wg1l);
    cudaGetSymbolAddress(&w1b_p, g_W1b);
    cudaGetSymbolAddress(&w2b_p, g_W2b);

    cudaFuncSetAttribute(moe_gemm_kernel<true>,
                         cudaFuncAttributeMaxDynamicSharedMemorySize, MOESMEM);
    cudaFuncSetAttribute(moe_gemm_kernel<false>,
                         cudaFuncAttributeMaxDynamicSharedMemorySize, MOESMEM);

    int nx  = Pn * Fn;
    int ng  = Fn * Gn;
    int nw1 = Nn * Fn * Hn;
    int nw2 = Nn * Hn * Fn;

    // Fork: W1/W2 converts run on side stream, parallel to x/Wg1 converts + gating.
    cudaStream_t s2;
    cudaEvent_t evFork, evJoin;
    cudaStreamCreateWithFlags(&s2, cudaStreamNonBlocking);
    cudaEventCreateWithFlags(&evFork, cudaEventDisableTiming);
    cudaEventCreateWithFlags(&evJoin, cudaEventDisableTiming);

    cudaEventRecord(evFork, 0);
    cudaStreamWaitEvent(s2, evFork, 0);
    cvt_kernel<<<(nw1 / 8 + 255) / 256, 256, 0, s2>>>(W1, (__nv_bfloat16*)w1b_p, nw1);
    cvt_kernel<<<(nw2 / 8 + 255) / 256, 256, 0, s2>>>(W2, (__nv_bfloat16*)w2b_p, nw2);
    cudaEventRecord(evJoin, s2);

    cvt_split_kernel<<<(nx / 8 + 255) / 256, 256>>>(x, (__nv_bfloat16*)xb_p,
                                                    (__nv_bfloat16*)xl_p, nx);
    cvt_split_kernel<<<(ng / 8 + 255) / 256, 256>>>(Wg1, (__nv_bfloat16*)wh_p,
                                                    (__nv_bfloat16*)wl_p, ng);

    gate1_tc_kernel<<<dim3((Pn + 127) / 128, Gn / 64), 256>>>(bg1);
    gate2_kernel<<<Pn / 8, 256>>>(Wg2, bg2);
    cap_kernel<<<dim3(Bn, Nn), 224>>>();
    init_out_kernel<<<Pn, 256>>>(x, b2, out);

    cudaStreamWaitEvent(0, evJoin, 0);   // join weight converts before GEMM1

    moe_gemm_kernel<true ><<<dim3(MR / 128, Hn / 128, Nn), 256, MOESMEM>>>(b1, out);
    moe_gemm_kernel<false><<<dim3(MR / 128, Fn / 128, Nn), 256, MOESMEM>>>(b2, out);

    cudaEventDestroy(evFork);
    cudaEventDestroy(evJoin);
    cudaStreamDestroy(s2);
}

// round 17
// speedup vs baseline: 1.0085x; 1.0085x over previous
#include <cuda_runtime.h>
#include <cuda_bf16.h>
#include <cstdint>

#define Tn   197
#define Bn   64
#define Fn   768
#define Gn   192
#define Nn   8
#define CAPn 49
#define Hn   3072
#define Pn   (Tn*Bn)
#define MRV  (Bn*CAPn)
#define MR   3200

__device__ __nv_bfloat16 g_xb [Pn*Fn];     // x hi (bf16)
__device__ __nv_bfloat16 g_xl [Pn*Fn];     // x lo residual (bf16)
__device__ __nv_bfloat16 g_wg1h[Fn*Gn];    // Wg1 hi
__device__ __nv_bfloat16 g_wg1l[Fn*Gn];    // Wg1 lo
__device__ __nv_bfloat16 g_W1b[Nn*Fn*Hn];
__device__ __nv_bfloat16 g_W2b[Nn*Hn*Fn];
__device__ float         g_gate[Pn*Gn];
__device__ float         g_cw  [Pn*Nn];
__device__ int           g_tok [Nn*MR];
__device__ float         g_wgt [Nn*MR];
__device__ __nv_bfloat16 g_H   [(size_t)Nn*MR*Hn];

// fp32 -> bf16, 8 elems/thread (2 independent float4 loads -> MLP 2)
__global__ void cvt_kernel(const float* __restrict__ s, __nv_bfloat16* __restrict__ d, int n)
{
    int i = (blockIdx.x * 256 + threadIdx.x) * 8;
    if (i < n) {
        float4 v0 = *(const float4*)(s + i);
        float4 v1 = *(const float4*)(s + i + 4);
        *(__nv_bfloat162*)(d + i)     = __floats2bfloat162_rn(v0.x, v0.y);
        *(__nv_bfloat162*)(d + i + 2) = __floats2bfloat162_rn(v0.z, v0.w);
        *(__nv_bfloat162*)(d + i + 4) = __floats2bfloat162_rn(v1.x, v1.y);
        *(__nv_bfloat162*)(d + i + 6) = __floats2bfloat162_rn(v1.z, v1.w);
    }
}

// fp32 -> (hi bf16, lo bf16 residual), 8 elems/thread (MLP 2)
__global__ void cvt_split_kernel(const float* __restrict__ s,
                                 __nv_bfloat16* __restrict__ hi,
                                 __nv_bfloat16* __restrict__ lo, int n)
{
    int i = (blockIdx.x * 256 + threadIdx.x) * 8;
    if (i < n) {
        float4 v0 = *(const float4*)(s + i);
        float4 v1 = *(const float4*)(s + i + 4);
        float f[8] = {v0.x, v0.y, v0.z, v0.w, v1.x, v1.y, v1.z, v1.w};
        __nv_bfloat16 h[8], l[8];
#pragma unroll
        for (int j = 0; j < 8; j++) {
            h[j] = __float2bfloat16(f[j]);
            l[j] = __float2bfloat16(f[j] - __bfloat162float(h[j]));
        }
#pragma unroll
        for (int j = 0; j < 8; j += 2) {
            *(__nv_bfloat162*)(hi + i + j) = *(__nv_bfloat162*)&h[j];
            *(__nv_bfloat162*)(lo + i + j) = *(__nv_bfloat162*)&l[j];
        }
    }
}

// -------- mma.sync helpers --------
__device__ __forceinline__ void ldsm4(uint32_t r[4], uint32_t addr)
{
    asm volatile("ldmatrix.sync.aligned.m8n8.x4.shared.b16 {%0,%1,%2,%3}, [%4];"
                 : "=r"(r[0]), "=r"(r[1]), "=r"(r[2]), "=r"(r[3]) : "r"(addr));
}
__device__ __forceinline__ void ldsm4t(uint32_t r[4], uint32_t addr)
{
    asm volatile("ldmatrix.sync.aligned.m8n8.x4.trans.shared.b16 {%0,%1,%2,%3}, [%4];"
                 : "=r"(r[0]), "=r"(r[1]), "=r"(r[2]), "=r"(r[3]) : "r"(addr));
}
__device__ __forceinline__ void mma16816(float c[4], const uint32_t a[4], uint32_t b0, uint32_t b1)
{
    asm volatile("mma.sync.aligned.m16n8k16.row.col.f32.bf16.bf16.f32 "
                 "{%0,%1,%2,%3},{%4,%5,%6,%7},{%8,%9},{%0,%1,%2,%3};"
                 : "+f"(c[0]), "+f"(c[1]), "+f"(c[2]), "+f"(c[3])
                 : "r"(a[0]), "r"(a[1]), "r"(a[2]), "r"(a[3]), "r"(b0), "r"(b1));
}
__device__ __forceinline__ void cpasync16(uint32_t saddr, const void* g, int sz)
{
    asm volatile("cp.async.cg.shared.global [%0], [%1], 16, %2;" :: "r"(saddr), "l"(g), "r"(sz));
}

// gate layer 1 via split-bf16 tensor cores
__global__ void __launch_bounds__(256) gate1_tc_kernel(const float* __restrict__ bg1)
{
    __shared__ __align__(16) __nv_bfloat16 sAh[2][128 * 24];
    __shared__ __align__(16) __nv_bfloat16 sAl[2][128 * 24];
    __shared__ __align__(16) __nv_bfloat16 sBh[2][16 * 72];
    __shared__ __align__(16) __nv_bfloat16 sBl[2][16 * 72];

    const int m0 = blockIdx.x * 128;
    const int n0 = blockIdx.y * 64;
    const int tid = threadIdx.x;
    const int lane = tid & 31;
    const int warp = tid >> 5;
    const int wm = warp >> 1, wn = warp & 1;

    int rowA = tid >> 1, cA = (tid & 1) * 8;
    int szA = (m0 + rowA < Pn) ? 16 : 0;
    int rA = (m0 + rowA < Pn) ? (m0 + rowA) : 0;
    const __nv_bfloat16* aph = g_xb + (size_t)rA * Fn + cA;
    const __nv_bfloat16* apl = g_xl + (size_t)rA * Fn + cA;
    int tb = tid & 127;
    int rowB = tb >> 3, cB = (tb & 7) * 8;
    const __nv_bfloat16* bp = (tid < 128 ? g_wg1h : g_wg1l) + (size_t)rowB * Gn + n0 + cB;

    uint32_t sAhB = (uint32_t)__cvta_generic_to_shared(&sAh[0][0]);
    uint32_t sAlB = (uint32_t)__cvta_generic_to_shared(&sAl[0][0]);
    uint32_t sBhB = (uint32_t)__cvta_generic_to_shared(&sBh[0][0]);
    uint32_t sBlB = (uint32_t)__cvta_generic_to_shared(&sBl[0][0]);
    const uint32_t stA = 128 * 24 * 2, stB = 16 * 72 * 2;
    uint32_t dAh = sAhB + (rowA * 24 + cA) * 2;
    uint32_t dAl = sAlB + (rowA * 24 + cA) * 2;
    uint32_t dB  = (tid < 128 ? sBhB : sBlB) + (rowB * 72 + cB) * 2;

    float acc[2][4][4] = {};
    constexpr int NK = Fn / 16;

    auto load_stage = [&](int buf, int kt) {
        int ko = kt * 16;
        cpasync16(dAh + buf * stA, aph + ko, szA);
        cpasync16(dAl + buf * stA, apl + ko, szA);
        cpasync16(dB  + buf * stB, bp + (size_t)ko * Gn, 16);
    };

    load_stage(0, 0);
    asm volatile("cp.async.commit_group;");

    uint32_t aoff = ((wm * 32 + (lane & 15)) * 24 + (lane >> 4) * 8) * 2;
    uint32_t boff = (((lane & 7) + ((lane >> 3) & 1) * 8) * 72 + wn * 32 + (lane >> 4) * 8) * 2;

    for (int kt = 0; kt < NK; ++kt) {
        if (kt + 1 < NK) load_stage((kt + 1) & 1, kt + 1);
        asm volatile("cp.async.commit_group;");
        asm volatile("cp.async.wait_group 1;");
        __syncthreads();

        int buf = kt & 1;
        uint32_t ah[2][4], al[2][4], bh[2][4], bl[2][4];
#pragma unroll
        for (int mi = 0; mi < 2; mi++) {
            ldsm4(ah[mi], sAhB + buf * stA + aoff + mi * 16 * 24 * 2);
            ldsm4(al[mi], sAlB + buf * stA + aoff + mi * 16 * 24 * 2);
        }
#pragma unroll
        for (int nj = 0; nj < 2; nj++) {
            ldsm4t(bh[nj], sBhB + buf * stB + boff + nj * 16 * 2);
            ldsm4t(bl[nj], sBlB + buf * stB + boff + nj * 16 * 2);
        }
#pragma unroll
        for (int mi = 0; mi < 2; mi++)
#pragma unroll
            for (int ni = 0; ni < 4; ni++) {
                int sl = ni >> 1, pp = (ni & 1) * 2;
                mma16816(acc[mi][ni], ah[mi], bh[sl][pp], bh[sl][pp + 1]);
                mma16816(acc[mi][ni], ah[mi], bl[sl][pp], bl[sl][pp + 1]);
                mma16816(acc[mi][ni], al[mi], bh[sl][pp], bh[sl][pp + 1]);
            }
        __syncthreads();
    }

    int gq = lane >> 2, t2 = lane & 3;
#pragma unroll
    for (int mi = 0; mi < 2; mi++) {
        int mlo = m0 + wm * 32 + mi * 16 + gq;
#pragma unroll
        for (int ni = 0; ni < 4; ni++) {
            int col = n0 + wn * 32 + ni * 8 + t2 * 2;
            float b0 = bg1[col], b1 = bg1[col + 1];
            if (mlo < Pn) {
                g_gate[(size_t)mlo * Gn + col]     = fmaxf(acc[mi][ni][0] + b0, 0.f);
                g_gate[(size_t)mlo * Gn + col + 1] = fmaxf(acc[mi][ni][1] + b1, 0.f);
            }
            if (mlo + 8 < Pn) {
                g_gate[(size_t)(mlo + 8) * Gn + col]     = fmaxf(acc[mi][ni][2] + b0, 0.f);
                g_gate[(size_t)(mlo + 8) * Gn + col + 1] = fmaxf(acc[mi][ni][3] + b1, 0.f);
            }
        }
    }
}

// gate layer 2 + softmax + top-2 (warp per token)
__global__ void gate2_kernel(const float* __restrict__ Wg2, const float* __restrict__ bg2)
{
    int tokw = blockIdx.x * 8 + (threadIdx.x >> 5);
    if (tokw >= Pn) return;
    int lane = threadIdx.x & 31;
    const float* g = g_gate + (size_t)tokw * Gn;

    float s[8] = {};
    for (int j = lane; j < Gn; j += 32) {
        float gv = g[j];
        float4 w0 = *(const float4*)(Wg2 + j * 8);
        float4 w1 = *(const float4*)(Wg2 + j * 8 + 4);
        s[0] += gv * w0.x; s[1] += gv * w0.y; s[2] += gv * w0.z; s[3] += gv * w0.w;
        s[4] += gv * w1.x; s[5] += gv * w1.y; s[6] += gv * w1.z; s[7] += gv * w1.w;
    }
#pragma unroll
    for (int e = 0; e < 8; e++)
#pragma unroll
        for (int o = 16; o; o >>= 1) s[e] += __shfl_xor_sync(0xffffffffu, s[e], o);

    if (lane == 0) {
        float l[8], mx = -1e30f;
#pragma unroll
        for (int e = 0; e < 8; e++) { l[e] = s[e] + bg2[e]; mx = fmaxf(mx, l[e]); }
        float p[8], sum = 0.f;
#pragma unroll
        for (int e = 0; e < 8; e++) { p[e] = expf(l[e] - mx); sum += p[e]; }
        float inv = 1.f / sum, gwv[8];
#pragma unroll
        for (int e = 0; e < 8; e++) gwv[e] = p[e] * inv;
        int i1 = 0;
#pragma unroll
        for (int e = 1; e < 8; e++) if (gwv[e] > gwv[i1]) i1 = e;
        int i2 = (i1 == 0) ? 1 : 0;
#pragma unroll
        for (int e = 0; e < 8; e++) if (e != i1 && gwv[e] > gwv[i2]) i2 = e;
#pragma unroll
        for (int e = 0; e < 8; e++)
            g_cw[(size_t)tokw * 8 + e] = (e == i1 || e == i2) ? gwv[e] : 0.f;
    }
}

// capacity selection per (b,n): top-CAP by (value desc, index asc)
__global__ void cap_kernel()
{
    int b = blockIdx.x, n = blockIdx.y;
    __shared__ unsigned sb[Tn];
    __shared__ float    svv[Tn];
    __shared__ unsigned char sel[Tn];
    __shared__ int scnt;

    int t = threadIdx.x;
    if (t < Tn) {
        float v = g_cw[(size_t)(t * Bn + b) * Nn + n];
        svv[t] = v;
        sb[t] = __float_as_uint(v);
    }
    __syncthreads();

    bool is = false; float v = 0.f;
    if (t < Tn) {
        unsigned bt = sb[t];
        int rank = 0;
        for (int j = 0; j < Tn; j++) {
            unsigned bj = sb[j];
            rank += (bj > bt) || (bj == bt && j < t);
        }
        v = svv[t];
        is = (rank < CAPn) && (v > 0.f);
        sel[t] = is ? 1 : 0;
        g_cw[(size_t)(t * Bn + b) * Nn + n] = is ? v : 0.f;
    }
    __syncthreads();
    if (t == 0) {
        int c = 0;
        for (int j = 0; j < Tn; j++) c += sel[j];
        scnt = c;
    }
    __syncthreads();

    if (t < Tn && is) {
        int slot = 0;
        for (int j = 0; j < t; j++) slot += sel[j];
        g_tok[n * MR + b * CAPn + slot] = t * Bn + b;
        g_wgt[n * MR + b * CAPn + slot] = v;
    }
    if (t >= scnt && t < CAPn) {
        g_tok[n * MR + b * CAPn + t] = -1;
        g_wgt[n * MR + b * CAPn + t] = 0.f;
    }
    if (b == 0 && t < (MR - MRV)) {
        g_tok[n * MR + MRV + t] = -1;
        g_wgt[n * MR + MRV + t] = 0.f;
    }
}

// out = -x + fw @ b2
__global__ void init_out_kernel(const float* __restrict__ x, const float* __restrict__ b2,
                                float* __restrict__ out)
{
    int p = blockIdx.x;
    __shared__ float fw[8];
    if (threadIdx.x < 8) fw[threadIdx.x] = g_cw[(size_t)p * 8 + threadIdx.x];
    __syncthreads();
    for (int f = threadIdx.x; f < Fn; f += blockDim.x) {
        float s = -x[(size_t)p * Fn + f];
#pragma unroll
        for (int n = 0; n < 8; n++) s += fw[n] * b2[n * Fn + f];
        out[(size_t)p * Fn + f] = s;
    }
}

// 128x128x32 tile, 256 threads, 2x4 warps, 64x32 warp tile, 4-stage cp.async pipeline.
// FIRST:  H = relu(gather(x) @ W1[n] + b1)   (K=768,  N=3072)
// !FIRST: out[tok] += wgt * (H @ W2[n])      (K=3072, N=768)
#define ASTG (128 * 40 * 2)
#define BSTG (32 * 136 * 2)
#define NSTAGE 4
#define MOESMEM (NSTAGE * (ASTG + BSTG))
template<bool FIRST>
__global__ void __launch_bounds__(256, 2) moe_gemm_kernel(const float* __restrict__ bias,
                                                          float* __restrict__ out)
{
    constexpr int KTOT = FIRST ? Fn : Hn;
    constexpr int NBW  = FIRST ? Hn : Fn;
    constexpr int NK   = KTOT / 32;

    extern __shared__ __align__(16) char dynsmem[];
    uint32_t smb = (uint32_t)__cvta_generic_to_shared(dynsmem);

    const int nexp = blockIdx.z;
    const int m0 = blockIdx.x * 128;
    const int n0 = blockIdx.y * 128;
    const int tid = threadIdx.x;
    const int lane = tid & 31;
    const int warp = tid >> 5;
    const int wm = warp >> 2, wn = warp & 3;

    const __nv_bfloat16* Wn_ = (FIRST ? g_W1b : g_W2b) + (size_t)nexp * KTOT * NBW;

    int rowA0 = tid >> 2;
    int rowA1 = rowA0 + 64;
    int koA = (tid & 3) * 8;
    const __nv_bfloat16 *ap0, *ap1;
    int sz0 = 16, sz1 = 16;
    if (FIRST) {
        int t0 = g_tok[nexp * MR + m0 + rowA0];
        int t1 = g_tok[nexp * MR + m0 + rowA1];
        if (t0 < 0) { sz0 = 0; t0 = 0; }
        if (t1 < 0) { sz1 = 0; t1 = 0; }
        ap0 = g_xb + (size_t)t0 * Fn + koA;
        ap1 = g_xb + (size_t)t1 * Fn + koA;
    } else {
        ap0 = g_H + (size_t)(nexp * MR + m0 + rowA0) * Hn + koA;
        ap1 = g_H + (size_t)(nexp * MR + m0 + rowA1) * Hn + koA;
    }

    int krB = tid >> 4;
    int nqB = (tid & 15) * 8;
    const __nv_bfloat16* bp0 = Wn_ + (size_t)krB * NBW + n0 + nqB;
    const __nv_bfloat16* bp1 = Wn_ + (size_t)(krB + 16) * NBW + n0 + nqB;

    uint32_t dA0 = (rowA0 * 40 + koA) * 2;
    uint32_t dA1 = (rowA1 * 40 + koA) * 2;
    uint32_t dB0 = (krB * 136 + nqB) * 2;
    uint32_t dB1 = ((krB + 16) * 136 + nqB) * 2;

    auto sAst = [&](int s) { return smb + s * ASTG; };
    auto sBst = [&](int s) { return smb + NSTAGE * ASTG + s * BSTG; };

    auto load_stage = [&](int s, int kt) {
        size_t ko = (size_t)kt * 32;
        cpasync16(sAst(s) + dA0, ap0 + ko, sz0);
        cpasync16(sAst(s) + dA1, ap1 + ko, sz1);
        cpasync16(sBst(s) + dB0, bp0 + ko * NBW, 16);
        cpasync16(sBst(s) + dB1, bp1 + ko * NBW, 16);
    };

    float acc[4][4][4] = {};

    load_stage(0, 0);
    asm volatile("cp.async.commit_group;");
    load_stage(1, 1);
    asm volatile("cp.async.commit_group;");
    load_stage(2, 2);
    asm volatile("cp.async.commit_group;");

    uint32_t aoff = ((wm * 64 + (lane & 15)) * 40 + (lane >> 4) * 8) * 2;
    uint32_t boff = (((lane & 7) + ((lane >> 3) & 1) * 8) * 136 + wn * 32 + (lane >> 4) * 8) * 2;

    int ld = 3;
    for (int kt = 0; kt < NK; ++kt) {
        asm volatile("cp.async.wait_group 2;");
        __syncthreads();
        if (ld < NK) {
            int ls = ld & 3;
            load_stage(ls, ld);
        }
        asm volatile("cp.async.commit_group;");
        ld++;

        int st = kt & 3;
        uint32_t aAddr = sAst(st) + aoff;
        uint32_t bAddr = sBst(st) + boff;
#pragma unroll
        for (int ks = 0; ks < 2; ++ks) {
            uint32_t a[4][4];
#pragma unroll
            for (int mi = 0; mi < 4; mi++) ldsm4(a[mi], aAddr + (mi * 16 * 40 + ks * 16) * 2);
            uint32_t bfr[2][4];
#pragma unroll
            for (int nj = 0; nj < 2; nj++) ldsm4t(bfr[nj], bAddr + (ks * 16 * 136 + nj * 16) * 2);
#pragma unroll
            for (int mi = 0; mi < 4; mi++)
#pragma unroll
                for (int ni = 0; ni < 4; ni++)
                    mma16816(acc[mi][ni], a[mi],
                             bfr[ni >> 1][(ni & 1) * 2], bfr[ni >> 1][(ni & 1) * 2 + 1]);
        }
    }

    int gq = lane >> 2, t2 = lane & 3;
    if (FIRST) {
#pragma unroll
        for (int mi = 0; mi < 4; mi++) {
            int mlo = m0 + wm * 64 + mi * 16 + gq;
#pragma unroll
            for (int ni = 0; ni < 4; ni++) {
                int col = n0 + wn * 32 + ni * 8 + t2 * 2;
                float bv0 = bias[nexp * Hn + col];
                float bv1 = bias[nexp * Hn + col + 1];
                *(__nv_bfloat162*)&g_H[(size_t)(nexp * MR + mlo) * Hn + col] =
                    __floats2bfloat162_rn(fmaxf(acc[mi][ni][0] + bv0, 0.f),
                                          fmaxf(acc[mi][ni][1] + bv1, 0.f));
                *(__nv_bfloat162*)&g_H[(size_t)(nexp * MR + mlo + 8) * Hn + col] =
                    __floats2bfloat162_rn(fmaxf(acc[mi][ni][2] + bv0, 0.f),
                                          fmaxf(acc[mi][ni][3] + bv1, 0.f));
            }
        }
    } else {
#pragma unroll
        for (int mi = 0; mi < 4; mi++) {
            int rlo = m0 + wm * 64 + mi * 16 + gq;
            int tokLo = g_tok[nexp * MR + rlo];
            int tokHi = g_tok[nexp * MR + rlo + 8];
            float wLo = g_wgt[nexp * MR + rlo];
            float wHi = g_wgt[nexp * MR + rlo + 8];
#pragma unroll
            for (int ni = 0; ni < 4; ni++) {
                int col = n0 + wn * 32 + ni * 8 + t2 * 2;
                if (tokLo >= 0) {
                    atomicAdd(out + (size_t)tokLo * Fn + col,     acc[mi][ni][0] * wLo);
                    atomicAdd(out + (size_t)tokLo * Fn + col + 1, acc[mi][ni][1] * wLo);
                }
                if (tokHi >= 0) {
                    atomicAdd(out + (size_t)tokHi * Fn + col,     acc[mi][ni][2] * wHi);
                    atomicAdd(out + (size_t)tokHi * Fn + col + 1, acc[mi][ni][3] * wHi);
                }
            }
        }
    }
}

extern "C" void kernel_launch(void* const* d_in, const int* in_sizes, int n_in,
                              void* d_out, int out_size)
{
    const float* x   = (const float*)d_in[0];
    const float* Wg1 = (const float*)d_in[1];
    const float* bg1 = (const float*)d_in[2];
    const float* Wg2 = (const float*)d_in[3];
    const float* bg2 = (const float*)d_in[4];
    const float* W1  = (const float*)d_in[5];
    const float* b1  = (const float*)d_in[6];
    const float* W2  = (const float*)d_in[7];
    const float* b2  = (const float*)d_in[8];
    float* out = (float*)d_out;

    void *xb_p, *xl_p, *wh_p, *wl_p, *w1b_p, *w2b_p;
    cudaGetSymbolAddress(&xb_p,  g_xb);
    cudaGetSymbolAddress(&xl_p,  g_xl);
    cudaGetSymbolAddress(&wh_p,  g_wg1h);
    cudaGetSymbolAddress(&wl_p,  g_wg1l);
    cudaGetSymbolAddress(&w1b_p, g_W1b);
    cudaGetSymbolAddress(&w2b_p, g_W2b);

    cudaFuncSetAttribute(moe_gemm_kernel<true>,
                         cudaFuncAttributeMaxDynamicSharedMemorySize, MOESMEM);
    cudaFuncSetAttribute(moe_gemm_kernel<false>,
                         cudaFuncAttributeMaxDynamicSharedMemorySize, MOESMEM);

    int nx  = Pn * Fn;
    int ng  = Fn * Gn;
    int nw1 = Nn * Fn * Hn;
    int nw2 = Nn * Hn * Fn;
    cvt_split_kernel<<<(nx / 8 + 255) / 256, 256>>>(x, (__nv_bfloat16*)xb_p,
                                                    (__nv_bfloat16*)xl_p, nx);
    cvt_split_kernel<<<(ng / 8 + 255) / 256, 256>>>(Wg1, (__nv_bfloat16*)wh_p,
                                                    (__nv_bfloat16*)wl_p, ng);
    cvt_kernel<<<(nw1 / 8 + 255) / 256, 256>>>(W1, (__nv_bfloat16*)w1b_p, nw1);
    cvt_kernel<<<(nw2 / 8 + 255) / 256, 256>>>(W2, (__nv_bfloat16*)w2b_p, nw2);

    gate1_tc_kernel<<<dim3((Pn + 127) / 128, Gn / 64), 256>>>(bg1);
    gate2_kernel<<<Pn / 8, 256>>>(Wg2, bg2);
    cap_kernel<<<dim3(Bn, Nn), 224>>>();
    init_out_kernel<<<Pn, 256>>>(x, b2, out);

    moe_gemm_kernel<true ><<<dim3(MR / 128, Hn / 128, Nn), 256, MOESMEM>>>(b1, out);
    moe_gemm_kernel<false><<<dim3(MR / 128, Fn / 128, Nn), 256, MOESMEM>>>(b2, out);
}